// round 7
// baseline (speedup 1.0000x reference)
#include <cuda_runtime.h>
#include <cuda_bf16.h>
#include <cstddef>
#include <cstdint>

#define S_LEN   2048
#define BATCH   32
#define IN_DIM  64
#define EMB_DIM 32
#define HID     256
#define XE      96
#define G4      1024
#define NGRP    16      // batch groups = clusters
#define CSIZE   8       // CTAs per cluster

typedef unsigned long long ull;

// ---- device scratch (module global: the sanctioned scratch mechanism) ----
__device__ float g_zx[(size_t)S_LEN * BATCH * G4];   // [t][b][row], 256 MiB

namespace {
struct EagerLoad {  // force module load before harness mem checkpoints
    EagerLoad() { void* p = nullptr; (void)cudaGetSymbolAddress(&p, g_zx); }
};
static EagerLoad eager_;
}

// ---- fast accurate activations --------------------------------------------
__device__ __forceinline__ float sigf(float x) {
    return __fdividef(1.f, 1.f + __expf(-x));
}
__device__ __forceinline__ float tanh_f(float x) {
    float ax = fabsf(x);
    float e  = __expf(-2.f * ax);            // in (0,1], never overflows
    return copysignf(__fdividef(1.f - e, 1.f + e), x);
}

// ---- f32x2 packed FMA (sm_10x; ptxas never auto-fuses this) ---------------
#define FMA2(d, a, b) \
    asm("fma.rn.f32x2 %0, %1, %2, %0;" : "+l"(d) : "l"(a), "l"(b))

__device__ __forceinline__ float hsum2(ull v) {
    float lo, hi;
    asm("mov.b64 {%0,%1}, %2;" : "=f"(lo), "=f"(hi) : "l"(v));
    return lo + hi;
}

__device__ __forceinline__ uint32_t smem_u32(const void* p) {
    uint32_t a;
    asm("{ .reg .u64 t; cvta.to.shared.u64 t, %1; cvt.u32.u64 %0, t; }"
        : "=r"(a) : "l"(p));
    return a;
}
__device__ __forceinline__ void st_cluster_f32(uint32_t laddr, uint32_t rank, float v) {
    asm volatile(
        "{\n\t.reg .u32 ra;\n\t"
        "mapa.shared::cluster.u32 ra, %0, %1;\n\t"
        "st.shared::cluster.f32 [ra], %2;\n\t}"
        :: "r"(laddr), "r"(rank), "f"(v) : "memory");
}
__device__ __forceinline__ void mbar_arrive_rank(uint32_t mbar_local, uint32_t rank) {
    asm volatile(
        "{\n\t.reg .b32 ra;\n\t"
        "mapa.shared::cluster.u32 ra, %0, %1;\n\t"
        "mbarrier.arrive.release.cluster.shared::cluster.b64 _, [ra];\n\t}"
        :: "r"(mbar_local), "r"(rank) : "memory");
}
__device__ __forceinline__ void mbar_wait(uint32_t mbar, uint32_t parity) {
    asm volatile(
        "{\n\t.reg .pred P;\n"
        "WL_%=:\n\t"
        "mbarrier.try_wait.parity.acquire.cluster.shared::cta.b64 P, [%0], %1, 0x989680;\n\t"
        "@!P bra WL_%=;\n\t}"
        :: "r"(mbar), "r"(parity) : "memory");
}

// ---------------------------------------------------------------------------
// Kernel A: zx[t][b][row] = bias[row] + sum_i [x|emb][b][t][i] * W_ih[row][i]
// grid (16 row-tiles, 2048 t), 256 threads, FFMA2.
// ---------------------------------------------------------------------------
__global__ void __launch_bounds__(256) zx_kernel(
    const float* __restrict__ x, const float* __restrict__ emb,
    const float* __restrict__ W_ih, const float* __restrict__ bias)
{
    const int t = blockIdx.y, rbase = blockIdx.x * 64, tid = threadIdx.x;

    __shared__ __align__(16) float xe_s[BATCH][100];
    __shared__ __align__(16) float W_s[64][100];

    for (int idx = tid; idx < BATCH * IN_DIM; idx += 256) {
        int b = idx >> 6, i = idx & 63;
        xe_s[b][i] = x[((size_t)b * S_LEN + t) * IN_DIM + i];
    }
    for (int idx = tid; idx < BATCH * EMB_DIM; idx += 256) {
        int b = idx >> 5, i = idx & 31;
        xe_s[b][IN_DIM + i] = emb[((size_t)b * S_LEN + t) * EMB_DIM + i];
    }
    for (int idx = tid; idx < 64 * XE; idx += 256) {
        int r = idx / XE, i = idx - r * XE;
        W_s[r][i] = W_ih[(size_t)(rbase + r) * XE + i];
    }
    __syncthreads();

    const int m = tid & 15, b0 = (tid >> 4) * 2;

    ull acc[4][2][2];
#pragma unroll
    for (int j = 0; j < 4; ++j)
#pragma unroll
        for (int b = 0; b < 2; ++b)
            acc[j][b][0] = acc[j][b][1] = 0ull;

    const ulonglong2* xv0 = reinterpret_cast<const ulonglong2*>(&xe_s[b0][0]);
    const ulonglong2* xv1 = reinterpret_cast<const ulonglong2*>(&xe_s[b0 + 1][0]);
#pragma unroll
    for (int k4 = 0; k4 < XE / 4; ++k4) {
        ulonglong2 xa = xv0[k4], xb = xv1[k4];
#pragma unroll
        for (int j = 0; j < 4; ++j) {
            ulonglong2 w = reinterpret_cast<const ulonglong2*>(&W_s[m + 16 * j][0])[k4];
            FMA2(acc[j][0][0], w.x, xa.x);
            FMA2(acc[j][0][1], w.y, xa.y);
            FMA2(acc[j][1][0], w.x, xb.x);
            FMA2(acc[j][1][1], w.y, xb.y);
        }
    }
#pragma unroll
    for (int j = 0; j < 4; ++j) {
        int row = rbase + m + 16 * j;
        float bv = __ldg(&bias[row]);
        size_t base = ((size_t)t * BATCH + b0) * G4 + row;
        g_zx[base]      = hsum2(acc[j][0][0]) + hsum2(acc[j][0][1]) + bv;
        g_zx[base + G4] = hsum2(acc[j][1][0]) + hsum2(acc[j][1][1]) + bv;
    }
}

// ---------------------------------------------------------------------------
// Kernel B: persistent LSTM. 16 independent 8-CTA clusters (2 batches each).
// W_hh slice register-resident: thread (khalf, r) owns row r (gate g=r>>5,
// unit u0+(r&31)) over k in [khalf*128, khalf*128+128) = 64 f32x2 pairs.
// h exchanged via DSMEM scatter + mbarrier (release/acquire), double-buffered.
// ---------------------------------------------------------------------------
__global__ void __launch_bounds__(256, 1) __cluster_dims__(CSIZE, 1, 1)
lstm_kernel(const float* __restrict__ W_hh, float* __restrict__ out)
{
    // hbuf[buf][k-pair][4]: {h_b0[2k], h_b0[2k+1], h_b1[2k], h_b1[2k+1]}
    __shared__ __align__(16) float hbuf[2][HID / 2][4];
    __shared__ __align__(16) float part[2][2][128];       // [khalf][b][r]
    __shared__ __align__(8)  ull   mbar[2];

    const int tid = threadIdx.x;
    const int grp = blockIdx.x / CSIZE;
    uint32_t rank;
    asm("mov.u32 %0, %%cluster_ctarank;" : "=r"(rank));
    const int b0 = grp * 2;
    const int u0 = (int)rank * 32;

    const uint32_t mbar_u32[2] = { smem_u32(&mbar[0]), smem_u32(&mbar[1]) };
    if (tid == 0) {
        asm volatile("mbarrier.init.shared.b64 [%0], %1;" :: "r"(mbar_u32[0]), "r"(CSIZE) : "memory");
        asm volatile("mbarrier.init.shared.b64 [%0], %1;" :: "r"(mbar_u32[1]), "r"(CSIZE) : "memory");
    }
    __syncthreads();
    // all mbarriers in the cluster must be initialized before any remote arrive
    asm volatile("barrier.cluster.arrive.aligned;" ::: "memory");
    asm volatile("barrier.cluster.wait.aligned;"   ::: "memory");

    const int r     = tid & 127;
    const int khalf = tid >> 7;
    const int g     = r >> 5, uu = r & 31;
    const int row   = g * HID + u0 + uu;          // global gate-row

    // ---- load W slice into registers: 64 f32x2 pairs (128 regs) ----
    ull Wr[64];
    {
        const ulonglong2* wsrc = reinterpret_cast<const ulonglong2*>(
            W_hh + (size_t)row * HID + khalf * 128);
#pragma unroll
        for (int i = 0; i < 32; ++i) {
            ulonglong2 v = __ldg(&wsrc[i]);
            Wr[2 * i]     = v.x;
            Wr[2 * i + 1] = v.y;
        }
    }

    // gate-thread constants (tid < 64): b = tid>>5, u = tid&31
    const int gb   = b0 + (tid >> 5);
    const int gu   = u0 + (tid & 31);
    const uint32_t hoff = ((uint32_t)((gu >> 1) * 4 + ((tid >> 5) << 1) + (gu & 1))) * 4u;
    const uint32_t hb_base[2] = { smem_u32(&hbuf[0][0][0]), smem_u32(&hbuf[1][0][0]) };
    float c_reg = 0.f;

    const float* zx_base = g_zx + (size_t)b0 * G4 + row;

    for (int t = 0; t < S_LEN; ++t) {
        // prefetch zx (issued before the wait; latency sleeps through it)
        float zxa = 0.f, zxb = 0.f;
        if (khalf == 0) {
            const float* zp = zx_base + (size_t)t * (BATCH * G4);
            zxa = __ldcs(zp);
            zxb = __ldcs(zp + G4);
        }

        float pb0 = 0.f, pb1 = 0.f;
        if (t > 0) {
            mbar_wait(mbar_u32[(t - 1) & 1], ((t - 1) >> 1) & 1);

            const ulonglong2* hsrc = reinterpret_cast<const ulonglong2*>(
                &hbuf[(t - 1) & 1][khalf * 64][0]);
            ull a0 = 0ull, a1 = 0ull, a2 = 0ull, a3 = 0ull;
#pragma unroll
            for (int i = 0; i < 64; i += 2) {
                ulonglong2 h0 = hsrc[i];
                FMA2(a0, Wr[i], h0.x);
                FMA2(a1, Wr[i], h0.y);
                ulonglong2 h1 = hsrc[i + 1];
                FMA2(a2, Wr[i + 1], h1.x);
                FMA2(a3, Wr[i + 1], h1.y);
            }
            pb0 = hsum2(a0) + hsum2(a2);
            pb1 = hsum2(a1) + hsum2(a3);
        }
        if (khalf == 0) { pb0 += zxa; pb1 += zxb; }
        part[khalf][0][r] = pb0;
        part[khalf][1][r] = pb1;
        __syncthreads();   // all dot reads of hbuf[(t-1)&1] complete here

        const bool last = (t == S_LEN - 1);
        if (tid < 64) {
            const int b = tid >> 5, u = tid & 31;
            float zi = part[0][b][u]       + part[1][b][u];
            float zf = part[0][b][32 + u]  + part[1][b][32 + u];
            float zg = part[0][b][64 + u]  + part[1][b][64 + u];
            float zo = part[0][b][96 + u]  + part[1][b][96 + u];
            float c = sigf(zf) * c_reg + sigf(zi) * tanh_f(zg);
            float h = sigf(zo) * tanh_f(c);
            c_reg = c;

            __stcs(&out[((size_t)gb * S_LEN + t) * HID + gu], h);
            if (last) {
                size_t tail = (size_t)BATCH * S_LEN * HID;
                out[tail + gb * HID + gu] = h;                 // final h
                out[tail + BATCH * HID + gb * HID + gu] = c;   // final c
            } else {
                // scatter h(t) into hbuf[t&1] of every CTA in the cluster
                uint32_t laddr = hb_base[t & 1] + hoff;
#pragma unroll
                for (uint32_t pr = 0; pr < CSIZE; ++pr)
                    st_cluster_f32(laddr, pr, h);
            }
        }
        if (!last) {
            // FULL CTA barrier: orders (a) every thread's dot reads (WAR
            // safety vs peers' next-step scatter) and (b) gate threads' DSMEM
            // scatters, before the release-arrive fan-out below.
            __syncthreads();
            if (tid == 0) {
#pragma unroll
                for (uint32_t pr = 0; pr < CSIZE; ++pr)
                    mbar_arrive_rank(mbar_u32[t & 1], pr);
            }
        }
    }

    // No CTA may exit while a peer's remote store/arrive targeting this CTA's
    // SMEM could still be in flight (exit race => unspecified launch failure).
    asm volatile("barrier.cluster.arrive.aligned;" ::: "memory");
    asm volatile("barrier.cluster.wait.aligned;"   ::: "memory");
}

// ---------------------------------------------------------------------------
extern "C" void kernel_launch(void* const* d_in, const int* in_sizes, int n_in,
                              void* d_out, int out_size) {
    const float* x    = (const float*)d_in[0];
    const float* emb  = (const float*)d_in[1];
    const float* W_ih = (const float*)d_in[2];
    const float* W_hh = (const float*)d_in[3];
    const float* bias = (const float*)d_in[4];
    float* out = (float*)d_out;

    zx_kernel<<<dim3(16, S_LEN), 256>>>(x, emb, W_ih, bias);
    lstm_kernel<<<NGRP * CSIZE, 256>>>(W_hh, out);
}

// round 8
// speedup vs baseline: 2.5711x; 2.5711x over previous
#include <cuda_runtime.h>
#include <cuda_bf16.h>
#include <cstddef>
#include <cstdint>

#define S_LEN   2048
#define BATCH   32
#define IN_DIM  64
#define EMB_DIM 32
#define HID     256
#define XE      96
#define G4      1024
#define NGRP    16      // batch groups = clusters
#define CSIZE   8       // CTAs per cluster
#define TX_BYTES 2048   // per-step tx into each CTA's mbar: 8 src * 64 floats * 4B

typedef unsigned long long ull;

// ---- device scratch (module global: the sanctioned scratch mechanism) ----
__device__ float g_zx[(size_t)S_LEN * BATCH * G4];   // [t][b][row], 256 MiB

namespace {
struct EagerLoad {  // force module load before harness mem checkpoints
    EagerLoad() { void* p = nullptr; (void)cudaGetSymbolAddress(&p, g_zx); }
};
static EagerLoad eager_;
}

// ---- fast accurate activations --------------------------------------------
__device__ __forceinline__ float sigf(float x) {
    return __fdividef(1.f, 1.f + __expf(-x));
}
__device__ __forceinline__ float tanh_f(float x) {
    float ax = fabsf(x);
    float e  = __expf(-2.f * ax);            // in (0,1], never overflows
    return copysignf(__fdividef(1.f - e, 1.f + e), x);
}

// ---- f32x2 packed FMA (sm_10x; ptxas never auto-fuses this) ---------------
#define FMA2(d, a, b) \
    asm("fma.rn.f32x2 %0, %1, %2, %0;" : "+l"(d) : "l"(a), "l"(b))

__device__ __forceinline__ float hsum2(ull v) {
    float lo, hi;
    asm("mov.b64 {%0,%1}, %2;" : "=f"(lo), "=f"(hi) : "l"(v));
    return lo + hi;
}

__device__ __forceinline__ uint32_t smem_u32(const void* p) {
    uint32_t a;
    asm("{ .reg .u64 t; cvta.to.shared.u64 t, %1; cvt.u32.u64 %0, t; }"
        : "=r"(a) : "l"(p));
    return a;
}
__device__ __forceinline__ uint32_t mapa_u32(uint32_t laddr, uint32_t rank) {
    uint32_t ra;
    asm("mapa.shared::cluster.u32 %0, %1, %2;" : "=r"(ra) : "r"(laddr), "r"(rank));
    return ra;
}
// remote smem store + remote mbarrier tx-complete, hardware-ordered, async
__device__ __forceinline__ void st_async_f32(uint32_t raddr, uint32_t rmbar, float v) {
    asm volatile(
        "st.async.weak.shared::cluster.mbarrier::complete_tx::bytes.f32 [%0], %1, [%2];"
        :: "r"(raddr), "f"(v), "r"(rmbar) : "memory");
}
__device__ __forceinline__ void mbar_expect_tx(uint32_t mbar, uint32_t tx) {
    asm volatile("mbarrier.arrive.expect_tx.shared.b64 _, [%0], %1;"
                 :: "r"(mbar), "r"(tx) : "memory");
}
__device__ __forceinline__ void mbar_wait(uint32_t mbar, uint32_t parity) {
    asm volatile(
        "{\n\t.reg .pred P;\n"
        "WL_%=:\n\t"
        "mbarrier.try_wait.parity.acquire.cluster.shared::cta.b64 P, [%0], %1, 0x989680;\n\t"
        "@!P bra WL_%=;\n\t}"
        :: "r"(mbar), "r"(parity) : "memory");
}

// ---------------------------------------------------------------------------
// Kernel A: zx[t][b][row] = bias[row] + sum_i [x|emb][b][t][i] * W_ih[row][i]
// grid (16 row-tiles, 2048 t), 256 threads, FFMA2.
// ---------------------------------------------------------------------------
__global__ void __launch_bounds__(256) zx_kernel(
    const float* __restrict__ x, const float* __restrict__ emb,
    const float* __restrict__ W_ih, const float* __restrict__ bias)
{
    const int t = blockIdx.y, rbase = blockIdx.x * 64, tid = threadIdx.x;

    __shared__ __align__(16) float xe_s[BATCH][100];
    __shared__ __align__(16) float W_s[64][100];

    for (int idx = tid; idx < BATCH * IN_DIM; idx += 256) {
        int b = idx >> 6, i = idx & 63;
        xe_s[b][i] = x[((size_t)b * S_LEN + t) * IN_DIM + i];
    }
    for (int idx = tid; idx < BATCH * EMB_DIM; idx += 256) {
        int b = idx >> 5, i = idx & 31;
        xe_s[b][IN_DIM + i] = emb[((size_t)b * S_LEN + t) * EMB_DIM + i];
    }
    for (int idx = tid; idx < 64 * XE; idx += 256) {
        int r = idx / XE, i = idx - r * XE;
        W_s[r][i] = W_ih[(size_t)(rbase + r) * XE + i];
    }
    __syncthreads();

    const int m = tid & 15, b0 = (tid >> 4) * 2;

    ull acc[4][2][2];
#pragma unroll
    for (int j = 0; j < 4; ++j)
#pragma unroll
        for (int b = 0; b < 2; ++b)
            acc[j][b][0] = acc[j][b][1] = 0ull;

    const ulonglong2* xv0 = reinterpret_cast<const ulonglong2*>(&xe_s[b0][0]);
    const ulonglong2* xv1 = reinterpret_cast<const ulonglong2*>(&xe_s[b0 + 1][0]);
#pragma unroll
    for (int k4 = 0; k4 < XE / 4; ++k4) {
        ulonglong2 xa = xv0[k4], xb = xv1[k4];
#pragma unroll
        for (int j = 0; j < 4; ++j) {
            ulonglong2 w = reinterpret_cast<const ulonglong2*>(&W_s[m + 16 * j][0])[k4];
            FMA2(acc[j][0][0], w.x, xa.x);
            FMA2(acc[j][0][1], w.y, xa.y);
            FMA2(acc[j][1][0], w.x, xb.x);
            FMA2(acc[j][1][1], w.y, xb.y);
        }
    }
#pragma unroll
    for (int j = 0; j < 4; ++j) {
        int row = rbase + m + 16 * j;
        float bv = __ldg(&bias[row]);
        size_t base = ((size_t)t * BATCH + b0) * G4 + row;
        g_zx[base]      = hsum2(acc[j][0][0]) + hsum2(acc[j][0][1]) + bv;
        g_zx[base + G4] = hsum2(acc[j][1][0]) + hsum2(acc[j][1][1]) + bv;
    }
}

// ---------------------------------------------------------------------------
// Kernel B: persistent LSTM. 16 independent 8-CTA clusters (2 batches each).
// W_hh slice register-resident. h exchange: st.async to all 8 ranks signals
// each destination's mbarrier tx-count; one local arrive.expect_tx per step
// arms it. No fences, no remote arrives, no release drains.
// ---------------------------------------------------------------------------
__global__ void __launch_bounds__(256, 1) __cluster_dims__(CSIZE, 1, 1)
lstm_kernel(const float* __restrict__ W_hh, float* __restrict__ out)
{
    __shared__ __align__(16) float hbuf[2][2][HID];       // [buf][b][k]
    __shared__ __align__(16) float part[2][2][128];       // [khalf][b][r]
    __shared__ __align__(8)  ull   mbar[2];

    const int tid = threadIdx.x;
    const int grp = blockIdx.x / CSIZE;
    uint32_t rank;
    asm("mov.u32 %0, %%cluster_ctarank;" : "=r"(rank));
    const int b0 = grp * 2;
    const int u0 = (int)rank * 32;

    const uint32_t mbar_u32[2] = { smem_u32(&mbar[0]), smem_u32(&mbar[1]) };
    if (tid == 0) {
        asm volatile("mbarrier.init.shared.b64 [%0], 1;" :: "r"(mbar_u32[0]) : "memory");
        asm volatile("mbarrier.init.shared.b64 [%0], 1;" :: "r"(mbar_u32[1]) : "memory");
    }
    __syncthreads();
    // all mbarriers must be initialized before any peer's st.async can land
    asm volatile("barrier.cluster.arrive.aligned;" ::: "memory");
    asm volatile("barrier.cluster.wait.aligned;"   ::: "memory");

    const int r     = tid & 127;
    const int khalf = tid >> 7;
    const int g     = r >> 5, uu = r & 31;
    const int row   = g * HID + u0 + uu;          // global gate-row

    // ---- load W slice into registers: 64 f32x2 pairs (128 regs) ----
    ull Wr[64];
    {
        const ulonglong2* wsrc = reinterpret_cast<const ulonglong2*>(
            W_hh + (size_t)row * HID + khalf * 128);
#pragma unroll
        for (int i = 0; i < 32; ++i) {
            ulonglong2 v = __ldg(&wsrc[i]);
            Wr[2 * i]     = v.x;
            Wr[2 * i + 1] = v.y;
        }
    }

    // gate-thread constants (tid < 64): b = tid>>5, u = tid&31
    const int gb = b0 + (tid >> 5);
    const int gu = u0 + (tid & 31);
    const uint32_t hoff_b = (uint32_t)(((tid >> 5) * HID + gu) * 4);  // &hbuf[0][b][gu]
    const uint32_t hb_base[2] = { smem_u32(&hbuf[0][0][0]), smem_u32(&hbuf[1][0][0]) };
    float c_reg = 0.f;

    const float* zx_base = g_zx + (size_t)b0 * G4 + row;

    for (int t = 0; t < S_LEN; ++t) {
        const bool last = (t == S_LEN - 1);

        // prefetch zx (issued before the wait; latency sleeps through it)
        float zxa = 0.f, zxb = 0.f;
        if (khalf == 0) {
            const float* zp = zx_base + (size_t)t * (BATCH * G4);
            zxa = __ldcs(zp);
            zxb = __ldcs(zp + G4);
        }

        // arm this step's inbound barrier (its previous phase was consumed at
        // step t-1 by every local thread, so re-arming is race-free; tx
        // completes arriving before the expect is legal/commutative)
        if (tid == 64 && !last)
            mbar_expect_tx(mbar_u32[t & 1], TX_BYTES);

        float pb0 = 0.f, pb1 = 0.f;
        if (t > 0) {
            mbar_wait(mbar_u32[(t - 1) & 1], ((t - 1) >> 1) & 1);

            const int buf = (t - 1) & 1;
            const ulonglong2* h0 = reinterpret_cast<const ulonglong2*>(
                &hbuf[buf][0][khalf * 128]);
            const ulonglong2* h1 = reinterpret_cast<const ulonglong2*>(
                &hbuf[buf][1][khalf * 128]);
            ull a0 = 0ull, a1 = 0ull, a2 = 0ull, a3 = 0ull;
#pragma unroll
            for (int i = 0; i < 32; ++i) {
                ulonglong2 p = h0[i];
                FMA2(a0, Wr[2 * i],     p.x);
                FMA2(a1, Wr[2 * i + 1], p.y);
                ulonglong2 q = h1[i];
                FMA2(a2, Wr[2 * i],     q.x);
                FMA2(a3, Wr[2 * i + 1], q.y);
            }
            pb0 = hsum2(a0) + hsum2(a1);
            pb1 = hsum2(a2) + hsum2(a3);
        }
        if (khalf == 0) { pb0 += zxa; pb1 += zxb; }
        part[khalf][0][r] = pb0;
        part[khalf][1][r] = pb1;
        // Single per-step CTA barrier. Also provides all WAR ordering: our
        // scatter (below) follows every thread's dot reads of hbuf[(t-1)&1],
        // so no peer can overwrite that buffer (at step t+1) early.
        __syncthreads();

        if (tid < 64) {
            const int b = tid >> 5, u = tid & 31;
            float zi = part[0][b][u]       + part[1][b][u];
            float zf = part[0][b][32 + u]  + part[1][b][32 + u];
            float zg = part[0][b][64 + u]  + part[1][b][64 + u];
            float zo = part[0][b][96 + u]  + part[1][b][96 + u];
            float c = sigf(zf) * c_reg + sigf(zi) * tanh_f(zg);
            float h = sigf(zo) * tanh_f(c);
            c_reg = c;

            __stcs(&out[((size_t)gb * S_LEN + t) * HID + gu], h);
            if (last) {
                size_t tail = (size_t)BATCH * S_LEN * HID;
                out[tail + gb * HID + gu] = h;                 // final h
                out[tail + BATCH * HID + gb * HID + gu] = c;   // final c
            } else {
                // async scatter h(t) to hbuf[t&1] in every CTA; each store
                // carries 4B of tx-credit to that CTA's mbar[t&1]
                uint32_t laddr = hb_base[t & 1] + hoff_b;
                uint32_t lmbar = mbar_u32[t & 1];
#pragma unroll
                for (uint32_t pr = 0; pr < CSIZE; ++pr)
                    st_async_f32(mapa_u32(laddr, pr), mapa_u32(lmbar, pr), h);
            }
        }
        // no trailing barrier needed: the next step's mbar wait is the sync
    }

    // no CTA may exit while a peer's in-flight st.async could target its SMEM
    asm volatile("barrier.cluster.arrive.aligned;" ::: "memory");
    asm volatile("barrier.cluster.wait.aligned;"   ::: "memory");
}

// ---------------------------------------------------------------------------
extern "C" void kernel_launch(void* const* d_in, const int* in_sizes, int n_in,
                              void* d_out, int out_size) {
    const float* x    = (const float*)d_in[0];
    const float* emb  = (const float*)d_in[1];
    const float* W_ih = (const float*)d_in[2];
    const float* W_hh = (const float*)d_in[3];
    const float* bias = (const float*)d_in[4];
    float* out = (float*)d_out;

    zx_kernel<<<dim3(16, S_LEN), 256>>>(x, emb, W_ih, bias);
    lstm_kernel<<<NGRP * CSIZE, 256>>>(W_hh, out);
}